// round 12
// baseline (speedup 1.0000x reference)
#include <cuda_runtime.h>
#include <math.h>
#include <stdint.h>

#define Bc 32
#define Vc 8192
#define Tc 16
#define EMB_SCALE 22.627416997969522f
#define KSQ 16
#define KSF1 16
#define KSF2 64
#define KSL 4
#define KSE 64

__device__ float g_x[Bc * 512];
__device__ float g_qkvp[KSQ * Bc * 1536];
__device__ float g_ff1p[KSF1 * Bc * 2048];
__device__ float g_ff2p[KSF2 * Bc * 512];
__device__ float g_logp[KSL * Bc * Vc];
__device__ float g_embp[KSE * Bc * 512];
__device__ float g_logits[Bc * Vc];
__device__ float g_sample[Bc * Vc];
__device__ float g_ca[4 * Bc * 512];
__device__ float g_Kc[4 * Tc * Bc * 512];
__device__ float g_Vcc[4 * Tc * Bc * 512];

__device__ int g_count;
__device__ volatile int g_gen;

__shared__ float s_Xs[32 * 33];
__shared__ float s_Ws[256 * 33];
__shared__ float s_q[512];
__shared__ float s_o[512];

// replay-safe barrier: generation read fresh from g_gen every call
__device__ __forceinline__ void gsync() {
    __threadfence();
    __syncthreads();
    if (threadIdx.x == 0) {
        int gen = g_gen;
        if (atomicAdd(&g_count, 1) == (int)gridDim.x - 1) {
            g_count = 0;
            __threadfence();
            g_gen = gen + 1;
        } else {
            while (g_gen == gen) { }
        }
        __threadfence();
    }
    __syncthreads();
}

__device__ __forceinline__ float2 blockSum2(float a, float b) {
    __shared__ float sh[16];
    #pragma unroll
    for (int o = 16; o; o >>= 1) {
        a += __shfl_xor_sync(0xffffffffu, a, o);
        b += __shfl_xor_sync(0xffffffffu, b, o);
    }
    int w = threadIdx.x >> 5;
    if ((threadIdx.x & 31) == 0) { sh[w] = a; sh[8 + w] = b; }
    __syncthreads();
    float ra = sh[0]+sh[1]+sh[2]+sh[3]+sh[4]+sh[5]+sh[6]+sh[7];
    float rb = sh[8]+sh[9]+sh[10]+sh[11]+sh[12]+sh[13]+sh[14]+sh[15];
    __syncthreads();
    return make_float2(ra, rb);
}

__device__ __forceinline__ float2 blockMax2(float a, float b) {
    __shared__ float sh[16];
    #pragma unroll
    for (int o = 16; o; o >>= 1) {
        a = fmaxf(a, __shfl_xor_sync(0xffffffffu, a, o));
        b = fmaxf(b, __shfl_xor_sync(0xffffffffu, b, o));
    }
    int w = threadIdx.x >> 5;
    if ((threadIdx.x & 31) == 0) { sh[w] = a; sh[8 + w] = b; }
    __syncthreads();
    float ra = sh[0], rb = sh[8];
    #pragma unroll
    for (int i = 1; i < 8; i++) { ra = fmaxf(ra, sh[i]); rb = fmaxf(rb, sh[8+i]); }
    __syncthreads();
    return make_float2(ra, rb);
}

__device__ __forceinline__ float geluf(float x) {
    return 0.5f * x * (1.0f + erff(x * 0.70710678118654752f));
}

__device__ __forceinline__ void stage_X(const float* __restrict__ X, int ldx, int kc) {
    float (*Xs)[33] = (float(*)[33])s_Xs;
    int i = threadIdx.x;
    int r = i >> 3, kq = i & 7;
    float4 v = *(const float4*)(X + (size_t)r * ldx + kc + kq * 4);
    Xs[r][kq*4+0] = v.x; Xs[r][kq*4+1] = v.y; Xs[r][kq*4+2] = v.z; Xs[r][kq*4+3] = v.w;
}

__device__ __forceinline__ void stage_W_A(const float* __restrict__ W, int ldw, int nb, int kc) {
    float (*Ws)[33] = (float(*)[33])s_Ws;
    #pragma unroll
    for (int i = threadIdx.x; i < 2048; i += 256) {
        int c = i >> 3, kq = i & 7;
        float4 v = *(const float4*)(W + (size_t)(nb + c) * ldw + kc + kq * 4);
        Ws[c][kq*4+0] = v.x; Ws[c][kq*4+1] = v.y; Ws[c][kq*4+2] = v.z; Ws[c][kq*4+3] = v.w;
    }
}

__device__ __forceinline__ void stage_W_B(const float* __restrict__ W, int ldw, int nb, int kc) {
    float (*Wk)[260] = (float(*)[260])s_Ws;
    #pragma unroll
    for (int i = threadIdx.x; i < 2048; i += 256) {
        int k = i >> 6, cq = i & 63;
        float4 v = *(const float4*)(W + (size_t)(kc + k) * ldw + nb + cq * 4);
        *(float4*)&Wk[k][cq * 4] = v;
    }
}

__device__ __forceinline__ void inner_A(float acc[4][8], int r0, int c0) {
    float (*Xs)[33] = (float(*)[33])s_Xs;
    float (*Ws)[33] = (float(*)[33])s_Ws;
    #pragma unroll 4
    for (int k = 0; k < 32; k++) {
        float xa[4], wa[8];
        #pragma unroll
        for (int i = 0; i < 4; i++) xa[i] = Xs[r0 + i][k];
        #pragma unroll
        for (int j = 0; j < 8; j++) wa[j] = Ws[c0 + j][k];
        #pragma unroll
        for (int i = 0; i < 4; i++)
            #pragma unroll
            for (int j = 0; j < 8; j++) acc[i][j] += xa[i] * wa[j];
    }
}

__device__ __forceinline__ void inner_B(float acc[4][8], int r0, int c0) {
    float (*Xs)[33] = (float(*)[33])s_Xs;
    float (*Wk)[260] = (float(*)[260])s_Ws;
    #pragma unroll 4
    for (int k = 0; k < 32; k++) {
        float xa[4], wa[8];
        #pragma unroll
        for (int i = 0; i < 4; i++) xa[i] = Xs[r0 + i][k];
        #pragma unroll
        for (int j = 0; j < 8; j++) wa[j] = Wk[k][c0 + j];
        #pragma unroll
        for (int i = 0; i < 4; i++)
            #pragma unroll
            for (int j = 0; j < 8; j++) acc[i][j] += xa[i] * wa[j];
    }
}

__device__ __forceinline__ void store_acc(float acc[4][8], int r0, int c0,
                                          float* __restrict__ C, int ldc, int nb) {
    #pragma unroll
    for (int i = 0; i < 4; i++) {
        float4* p = (float4*)(C + (size_t)(r0 + i) * ldc + nb + c0);
        p[0] = make_float4(acc[i][0], acc[i][1], acc[i][2], acc[i][3]);
        p[1] = make_float4(acc[i][4], acc[i][5], acc[i][6], acc[i][7]);
    }
}

__global__ __launch_bounds__(256, 1) void mega(
        const float* __restrict__ enc,  const float* __restrict__ spec,
        const float* __restrict__ embw, const float* __restrict__ outw,
        const float* __restrict__ outb, const float* __restrict__ gum,
        const float* __restrict__ saqw, const float* __restrict__ saqb,
        const float* __restrict__ saow, const float* __restrict__ saob,
        const float* __restrict__ caqw, const float* __restrict__ caqb,
        const float* __restrict__ caow, const float* __restrict__ caob,
        const float* __restrict__ l1g,  const float* __restrict__ l1b,
        const float* __restrict__ l2g,  const float* __restrict__ l2b,
        const float* __restrict__ l3g,  const float* __restrict__ l3b,
        const float* __restrict__ w1,   const float* __restrict__ b1,
        const float* __restrict__ w2,   const float* __restrict__ b2,
        float* __restrict__ out) {
    int tid = threadIdx.x, blk = blockIdx.x, nbk = gridDim.x;
    int w = tid >> 5, lane = tid & 31;
    int r0 = (tid & 7) * 4, c0 = (tid >> 3) * 8;

    // ---- setup ----
    if (blk < 32) {
        for (int e = tid; e < 512; e += 256) g_x[blk * 512 + e] = spec[e];
        float* seq = out + (size_t)blk * (17 * Vc) + (size_t)16 * Vc;
        for (int v = tid; v < Vc; v += 256) seq[v] = (v == 0) ? 1.f : 0.f;
    }
    if (blk < 128) {
        int l = blk >> 5, b = blk & 31;
        for (int e = tid; e < 512; e += 256) s_q[e] = enc[b * 512 + e];
        __syncthreads();
        for (int e = w; e < 512; e += 8) {
            const float* wr = caqw + ((size_t)l * 1536 + 1024 + e) * 512;
            float a0=0,a1=0,a2=0,a3=0;
            for (int k = lane; k < 512; k += 128) {
                a0 += wr[k]*s_q[k];       a1 += wr[k+32]*s_q[k+32];
                a2 += wr[k+64]*s_q[k+64]; a3 += wr[k+96]*s_q[k+96];
            }
            float acc = a0+a1+a2+a3;
            #pragma unroll
            for (int o = 16; o; o >>= 1) acc += __shfl_xor_sync(0xffffffffu, acc, o);
            if (lane == 0) s_o[e] = acc + caqb[l * 1536 + 1024 + e];
        }
        __syncthreads();
        for (int e = w; e < 512; e += 8) {
            const float* wr = caow + ((size_t)l * 512 + e) * 512;
            float a0=0,a1=0,a2=0,a3=0;
            for (int k = lane; k < 512; k += 128) {
                a0 += wr[k]*s_o[k];       a1 += wr[k+32]*s_o[k+32];
                a2 += wr[k+64]*s_o[k+64]; a3 += wr[k+96]*s_o[k+96];
            }
            float acc = a0+a1+a2+a3;
            #pragma unroll
            for (int o = 16; o; o >>= 1) acc += __shfl_xor_sync(0xffffffffu, acc, o);
            if (lane == 0) g_ca[((size_t)l * 32 + b) * 512 + e] = acc + caob[l * 512 + e];
        }
    }
    gsync();

    for (int s = 0; s < Tc; s++) {
        for (int l = 0; l < 4; l++) {
            // P1: qkv partials (96 jobs = 6 nt x 16 ks)
            for (int j = blk; j < 6 * KSQ; j += nbk) {
                int ks = j & 15, nt = j >> 4;
                float acc[4][8] = {};
                __syncthreads();
                stage_X(g_x, 512, ks * 32);
                stage_W_A(saqw + (size_t)l * 1536 * 512, 512, nt * 256, ks * 32);
                __syncthreads();
                inner_A(acc, r0, c0);
                store_acc(acc, r0, c0, g_qkvp + (size_t)ks * 32 * 1536, 1536, nt * 256);
            }
            gsync();
            // P2: attn + out-proj + residual + LN1 + CA + LN2 (fused, 32 blocks)
            if (blk < 32) {
                int b = blk;
                const float* bp = saqb + l * 1536;
                for (int e = tid; e < 512; e += 256) {
                    float qq = bp[e], kk = bp[512 + e], vv = bp[1024 + e];
                    #pragma unroll
                    for (int p = 0; p < KSQ; p++) {
                        const float* qp = g_qkvp + ((size_t)p * 32 + b) * 1536;
                        qq += qp[e]; kk += qp[512 + e]; vv += qp[1024 + e];
                    }
                    s_q[e] = qq;
                    g_Kc [((size_t)(l * Tc + s) * Bc + b) * 512 + e] = kk;
                    g_Vcc[((size_t)(l * Tc + s) * Bc + b) * 512 + e] = vv;
                }
                __syncthreads();
                {   // warp-per-head attention -> s_o
                    float sc = -1e30f;
                    if (lane <= s) {
                        const float* kp = g_Kc + ((size_t)(l * Tc + lane) * Bc + b) * 512 + w * 64;
                        const float* qp = s_q + w * 64;
                        float a0 = 0.f, a1 = 0.f;
                        #pragma unroll
                        for (int d = 0; d < 64; d += 2) { a0 += qp[d]*kp[d]; a1 += qp[d+1]*kp[d+1]; }
                        sc = (a0 + a1) * 0.125f;
                    }
                    float m = sc;
                    #pragma unroll
                    for (int o = 16; o; o >>= 1) m = fmaxf(m, __shfl_xor_sync(0xffffffffu, m, o));
                    float ex = (lane <= s) ? expf(sc - m) : 0.f;
                    float sum = ex;
                    #pragma unroll
                    for (int o = 16; o; o >>= 1) sum += __shfl_xor_sync(0xffffffffu, sum, o);
                    float a = ex / sum;
                    float o0 = 0.f, o1 = 0.f;
                    for (int j = 0; j <= s; j++) {
                        float aj = __shfl_sync(0xffffffffu, a, j);
                        const float* vp = g_Vcc + ((size_t)(l * Tc + j) * Bc + b) * 512 + w * 64;
                        o0 += aj * vp[lane]; o1 += aj * vp[lane + 32];
                    }
                    s_o[w * 64 + lane] = o0; s_o[w * 64 + lane + 32] = o1;
                }
                __syncthreads();
                for (int e = w; e < 512; e += 8) {   // out-proj + residual -> s_q
                    const float* wr = saow + ((size_t)l * 512 + e) * 512;
                    float a0=0,a1=0,a2=0,a3=0;
                    for (int k = lane; k < 512; k += 128) {
                        a0 += wr[k]*s_o[k];       a1 += wr[k+32]*s_o[k+32];
                        a2 += wr[k+64]*s_o[k+64]; a3 += wr[k+96]*s_o[k+96];
                    }
                    float acc = a0+a1+a2+a3;
                    #pragma unroll
                    for (int o = 16; o; o >>= 1) acc += __shfl_xor_sync(0xffffffffu, acc, o);
                    if (lane == 0) s_q[e] = g_x[b * 512 + e] + acc + saob[l * 512 + e];
                }
                __syncthreads();
                float s1 = 0.f, s2 = 0.f;
                for (int e = tid; e < 512; e += 256) { float v = s_q[e]; s1 += v; s2 += v*v; }
                float2 r = blockSum2(s1, s2);
                float mean = r.x * (1.f/512.f);
                float rstd = rsqrtf(r.y * (1.f/512.f) - mean*mean + 1e-5f);
                for (int e = tid; e < 512; e += 256)
                    s_o[e] = (s_q[e]-mean)*rstd*l1g[l*512+e] + l1b[l*512+e]
                           + g_ca[((size_t)l*32+b)*512+e];
                __syncthreads();
                float t1 = 0.f, t2 = 0.f;
                for (int e = tid; e < 512; e += 256) { float v = s_o[e]; t1 += v; t2 += v*v; }
                r = blockSum2(t1, t2);
                mean = r.x * (1.f/512.f);
                rstd = rsqrtf(r.y * (1.f/512.f) - mean*mean + 1e-5f);
                for (int e = tid; e < 512; e += 256)
                    g_x[b*512+e] = (s_o[e]-mean)*rstd*l2g[l*512+e] + l2b[l*512+e];
            }
            gsync();
            // P5: ff1 partials (128 jobs)
            for (int j = blk; j < 8 * KSF1; j += nbk) {
                int ks = j & 15, nt = j >> 4;
                float acc[4][8] = {};
                __syncthreads();
                stage_X(g_x, 512, ks * 32);
                stage_W_A(w1 + (size_t)l * 2048 * 512, 512, nt * 256, ks * 32);
                __syncthreads();
                inner_A(acc, r0, c0);
                store_acc(acc, r0, c0, g_ff1p + (size_t)ks * 32 * 2048, 2048, nt * 256);
            }
            gsync();
            // P7: ff2 partials with folded gelu (128 jobs)
            for (int j = blk; j < 2 * KSF2; j += nbk) {
                int nt = j & 1, ks = j >> 1;
                int kc = ks * 32;
                float acc[4][8] = {};
                __syncthreads();
                {
                    float (*Xs)[33] = (float(*)[33])s_Xs;
                    for (int i = tid; i < 1024; i += 256) {
                        int r = i >> 5, k = i & 31;
                        float u = b1[l * 2048 + kc + k];
                        #pragma unroll
                        for (int p = 0; p < KSF1; p++)
                            u += g_ff1p[((size_t)(p * 32) + r) * 2048 + kc + k];
                        Xs[r][k] = geluf(u);
                    }
                }
                stage_W_A(w2 + (size_t)l * 512 * 2048, 2048, nt * 256, kc);
                __syncthreads();
                inner_A(acc, r0, c0);
                store_acc(acc, r0, c0, g_ff2p + (size_t)ks * 32 * 512, 512, nt * 256);
            }
            gsync();
            // P8: residual + LN3 (32 blocks)
            if (blk < 32) {
                int b = blk;
                for (int e = tid; e < 512; e += 256) {
                    float v = g_x[b * 512 + e] + b2[l * 512 + e];
                    #pragma unroll
                    for (int p = 0; p < KSF2; p++) v += g_ff2p[((size_t)p * 32 + b) * 512 + e];
                    s_q[e] = v;
                }
                __syncthreads();
                float s1 = 0.f, s2 = 0.f;
                for (int e = tid; e < 512; e += 256) { float v = s_q[e]; s1 += v; s2 += v*v; }
                float2 r = blockSum2(s1, s2);
                float mean = r.x * (1.f/512.f);
                float rstd = rsqrtf(r.y * (1.f/512.f) - mean*mean + 1e-5f);
                for (int e = tid; e < 512; e += 256)
                    g_x[b*512+e] = (s_q[e]-mean)*rstd*l3g[l*512+e] + l3b[l*512+e];
            }
            gsync();
        }
        // P9: logits partials (128 jobs)
        for (int j = blk; j < 32 * KSL; j += nbk) {
            int ks = j & 3, nt = j >> 2;
            float acc[4][8] = {};
            for (int kc = ks * 128; kc < ks * 128 + 128; kc += 32) {
                __syncthreads();
                stage_X(g_x, 512, kc);
                stage_W_A(outw, 512, nt * 256, kc);
                __syncthreads();
                inner_A(acc, r0, c0);
            }
            store_acc(acc, r0, c0, g_logp + (size_t)ks * 32 * Vc, Vc, nt * 256);
        }
        gsync();
        // P10: softmaxes + outputs + sample (32 blocks)
        if (blk < 32) {
            int b = blk;
            const float* gp = gum + ((size_t)s * Bc + b) * Vc;
            float* lg = g_logits + (size_t)b * Vc;
            float mx1 = -1e30f, mx2 = -1e30f;
            for (int v = tid; v < Vc; v += 256) {
                float x = outb[v];
                #pragma unroll
                for (int p = 0; p < KSL; p++) x += g_logp[((size_t)p * 32 + b) * Vc + v];
                lg[v] = x;
                mx1 = fmaxf(mx1, x);
                mx2 = fmaxf(mx2, x + gp[v]);
            }
            float2 M = blockMax2(mx1, mx2);
            float z1 = 0.f, z2 = 0.f;
            for (int v = tid; v < Vc; v += 256) {
                float x = lg[v];
                z1 += expf(x - M.x);
                z2 += expf(x + gp[v] - M.y);
            }
            float2 Z = blockSum2(z1, z2);
            float i1 = 1.f / Z.x, i2 = 1.f / Z.y;
            float* seq = out + (size_t)b * (17 * Vc) + (size_t)s * Vc;
            float* dst = out + (size_t)Bc * 17 * Vc + ((size_t)s * Bc + b) * Vc;
            float* smp = g_sample + (size_t)b * Vc;
            for (int v = tid; v < Vc; v += 256) {
                float x = lg[v];
                dst[v] = expf(x - M.x) * i1;
                float sv = expf(x + gp[v] - M.y) * i2;
                seq[v] = sv;
                smp[v] = sv;
            }
        }
        gsync();
        if (s < Tc - 1) {
            // P11: embed partials (128 jobs)
            for (int j = blk; j < 2 * KSE; j += nbk) {
                int nt = j & 1, ks = j >> 1;
                float acc[4][8] = {};
                for (int kc = ks * 128; kc < ks * 128 + 128; kc += 32) {
                    __syncthreads();
                    stage_X(g_sample, Vc, kc);
                    stage_W_B(embw, 512, nt * 256, kc);
                    __syncthreads();
                    inner_B(acc, r0, c0);
                }
                store_acc(acc, r0, c0, g_embp + (size_t)ks * 32 * 512, 512, nt * 256);
            }
            gsync();
            // P12: x = sum(embed partials) * sqrt(E) (32 blocks)
            if (blk < 32) {
                int b = blk;
                for (int e = tid; e < 512; e += 256) {
                    float a = 0.f;
                    #pragma unroll
                    for (int p = 0; p < KSE; p++) a += g_embp[((size_t)p * 32 + b) * 512 + e];
                    g_x[b * 512 + e] = a * EMB_SCALE;
                }
            }
            gsync();
        }
    }
}

extern "C" void kernel_launch(void* const* d_in, const int* in_sizes, int n_in,
                              void* d_out, int out_size) {
    const float* enc  = (const float*)d_in[0];
    const float* spec = (const float*)d_in[1];
    const float* embw = (const float*)d_in[2];
    const float* outw = (const float*)d_in[3];
    const float* outb = (const float*)d_in[4];
    const float* gum  = (const float*)d_in[5];
    const float* saqw = (const float*)d_in[6];
    const float* saqb = (const float*)d_in[7];
    const float* saow = (const float*)d_in[8];
    const float* saob = (const float*)d_in[9];
    const float* caqw = (const float*)d_in[10];
    const float* caqb = (const float*)d_in[11];
    const float* caow = (const float*)d_in[12];
    const float* caob = (const float*)d_in[13];
    const float* l1g  = (const float*)d_in[14];
    const float* l1b  = (const float*)d_in[15];
    const float* l2g  = (const float*)d_in[16];
    const float* l2b  = (const float*)d_in[17];
    const float* l3g  = (const float*)d_in[18];
    const float* l3b  = (const float*)d_in[19];
    const float* w1   = (const float*)d_in[20];
    const float* b1   = (const float*)d_in[21];
    const float* w2   = (const float*)d_in[22];
    const float* b2   = (const float*)d_in[23];

    int dev = 0;
    cudaGetDevice(&dev);
    int sms = 0;
    cudaDeviceGetAttribute(&sms, cudaDevAttrMultiProcessorCount, dev);
    if (sms < 1) sms = 148;
    if (sms > 256) sms = 256;

    mega<<<sms, 256>>>(enc, spec, embw, outw, outb, gum,
                       saqw, saqb, saow, saob, caqw, caqb, caow, caob,
                       l1g, l1b, l2g, l2b, l3g, l3b, w1, b1, w2, b2,
                       (float*)d_out);
}

// round 13
// speedup vs baseline: 2.2133x; 2.2133x over previous
#include <cuda_runtime.h>
#include <math.h>
#include <stdint.h>

#define Bc 32
#define Vc 8192
#define Tc 16
#define EMB_SCALE 22.627416997969522f
#define KSQ 16
#define KSO 16
#define KSF1 16
#define KSF2 64
#define KSL 4
#define KSE 64

__device__ float g_x[Bc * 512];
__device__ float g_attn_o[Bc * 512];
__device__ float g_qkvp[KSQ * Bc * 1536];
__device__ float g_opp[KSO * Bc * 512];
__device__ float g_ff1p[KSF1 * Bc * 2048];
__device__ float g_ff2p[KSF2 * Bc * 512];
__device__ float g_logp[KSL * Bc * Vc];
__device__ float g_embp[KSE * Bc * 512];
__device__ float g_logits[Bc * Vc];
__device__ float g_sample[Bc * Vc];
__device__ float g_ca[4 * Bc * 512];
__device__ float g_Kc[4 * Tc * Bc * 512];
__device__ float g_Vcc[4 * Tc * Bc * 512];

__device__ volatile int g_flags[256];
__device__ volatile int g_gen;

__shared__ float s_Xs[32 * 33];
__shared__ float s_Ws[256 * 33];
__shared__ float s_q[512];
__shared__ float s_o[512];

// Parallel tree barrier. Replay-safe because g_flags/g_gen are reset to 0 at
// kernel exit, so every launch starts from identical state.
__device__ __forceinline__ void gsync(int& gen) {
    gen++;
    __threadfence();
    __syncthreads();
    if (blockIdx.x == 0) {
        if (threadIdx.x > 0 && threadIdx.x < (int)gridDim.x) {
            while (g_flags[threadIdx.x] < gen) { }
        }
        __syncthreads();                 // all arrivals observed
        if (threadIdx.x == 0) { __threadfence(); g_gen = gen; }
    } else {
        if (threadIdx.x == 0) {
            g_flags[blockIdx.x] = gen;
            while (g_gen < gen) { }
        }
    }
    __threadfence();
    __syncthreads();
}

__device__ __forceinline__ float2 blockSum2(float a, float b) {
    __shared__ float sh[16];
    #pragma unroll
    for (int o = 16; o; o >>= 1) {
        a += __shfl_xor_sync(0xffffffffu, a, o);
        b += __shfl_xor_sync(0xffffffffu, b, o);
    }
    int w = threadIdx.x >> 5;
    if ((threadIdx.x & 31) == 0) { sh[w] = a; sh[8 + w] = b; }
    __syncthreads();
    float ra = sh[0]+sh[1]+sh[2]+sh[3]+sh[4]+sh[5]+sh[6]+sh[7];
    float rb = sh[8]+sh[9]+sh[10]+sh[11]+sh[12]+sh[13]+sh[14]+sh[15];
    __syncthreads();
    return make_float2(ra, rb);
}

__device__ __forceinline__ float2 blockMax2(float a, float b) {
    __shared__ float sh[16];
    #pragma unroll
    for (int o = 16; o; o >>= 1) {
        a = fmaxf(a, __shfl_xor_sync(0xffffffffu, a, o));
        b = fmaxf(b, __shfl_xor_sync(0xffffffffu, b, o));
    }
    int w = threadIdx.x >> 5;
    if ((threadIdx.x & 31) == 0) { sh[w] = a; sh[8 + w] = b; }
    __syncthreads();
    float ra = sh[0], rb = sh[8];
    #pragma unroll
    for (int i = 1; i < 8; i++) { ra = fmaxf(ra, sh[i]); rb = fmaxf(rb, sh[8+i]); }
    __syncthreads();
    return make_float2(ra, rb);
}

__device__ __forceinline__ float geluf(float x) {
    return 0.5f * x * (1.0f + erff(x * 0.70710678118654752f));
}

__device__ __forceinline__ void stage_X(const float* __restrict__ X, int ldx, int kc) {
    float (*Xs)[33] = (float(*)[33])s_Xs;
    int i = threadIdx.x;
    int r = i >> 3, kq = i & 7;
    float4 v = *(const float4*)(X + (size_t)r * ldx + kc + kq * 4);
    Xs[r][kq*4+0] = v.x; Xs[r][kq*4+1] = v.y; Xs[r][kq*4+2] = v.z; Xs[r][kq*4+3] = v.w;
}

__device__ __forceinline__ void stage_W_A(const float* __restrict__ W, int ldw, int nb, int kc) {
    float (*Ws)[33] = (float(*)[33])s_Ws;
    #pragma unroll
    for (int i = threadIdx.x; i < 2048; i += 256) {
        int c = i >> 3, kq = i & 7;
        float4 v = *(const float4*)(W + (size_t)(nb + c) * ldw + kc + kq * 4);
        Ws[c][kq*4+0] = v.x; Ws[c][kq*4+1] = v.y; Ws[c][kq*4+2] = v.z; Ws[c][kq*4+3] = v.w;
    }
}

__device__ __forceinline__ void stage_W_B(const float* __restrict__ W, int ldw, int nb, int kc) {
    float (*Wk)[260] = (float(*)[260])s_Ws;
    #pragma unroll
    for (int i = threadIdx.x; i < 2048; i += 256) {
        int k = i >> 6, cq = i & 63;
        float4 v = *(const float4*)(W + (size_t)(kc + k) * ldw + nb + cq * 4);
        *(float4*)&Wk[k][cq * 4] = v;
    }
}

__device__ __forceinline__ void inner_A(float acc[4][8], int r0, int c0) {
    float (*Xs)[33] = (float(*)[33])s_Xs;
    float (*Ws)[33] = (float(*)[33])s_Ws;
    #pragma unroll 4
    for (int k = 0; k < 32; k++) {
        float xa[4], wa[8];
        #pragma unroll
        for (int i = 0; i < 4; i++) xa[i] = Xs[r0 + i][k];
        #pragma unroll
        for (int j = 0; j < 8; j++) wa[j] = Ws[c0 + j][k];
        #pragma unroll
        for (int i = 0; i < 4; i++)
            #pragma unroll
            for (int j = 0; j < 8; j++) acc[i][j] += xa[i] * wa[j];
    }
}

__device__ __forceinline__ void inner_B(float acc[4][8], int r0, int c0) {
    float (*Xs)[33] = (float(*)[33])s_Xs;
    float (*Wk)[260] = (float(*)[260])s_Ws;
    #pragma unroll 4
    for (int k = 0; k < 32; k++) {
        float xa[4], wa[8];
        #pragma unroll
        for (int i = 0; i < 4; i++) xa[i] = Xs[r0 + i][k];
        #pragma unroll
        for (int j = 0; j < 8; j++) wa[j] = Wk[k][c0 + j];
        #pragma unroll
        for (int i = 0; i < 4; i++)
            #pragma unroll
            for (int j = 0; j < 8; j++) acc[i][j] += xa[i] * wa[j];
    }
}

__device__ __forceinline__ void store_acc(float acc[4][8], int r0, int c0,
                                          float* __restrict__ C, int ldc, int nb) {
    #pragma unroll
    for (int i = 0; i < 4; i++) {
        float4* p = (float4*)(C + (size_t)(r0 + i) * ldc + nb + c0);
        p[0] = make_float4(acc[i][0], acc[i][1], acc[i][2], acc[i][3]);
        p[1] = make_float4(acc[i][4], acc[i][5], acc[i][6], acc[i][7]);
    }
}

__global__ __launch_bounds__(256, 1) void mega(
        const float* __restrict__ enc,  const float* __restrict__ spec,
        const float* __restrict__ embw, const float* __restrict__ outw,
        const float* __restrict__ outb, const float* __restrict__ gum,
        const float* __restrict__ saqw, const float* __restrict__ saqb,
        const float* __restrict__ saow, const float* __restrict__ saob,
        const float* __restrict__ caqw, const float* __restrict__ caqb,
        const float* __restrict__ caow, const float* __restrict__ caob,
        const float* __restrict__ l1g,  const float* __restrict__ l1b,
        const float* __restrict__ l2g,  const float* __restrict__ l2b,
        const float* __restrict__ l3g,  const float* __restrict__ l3b,
        const float* __restrict__ w1,   const float* __restrict__ b1,
        const float* __restrict__ w2,   const float* __restrict__ b2,
        float* __restrict__ out) {
    int tid = threadIdx.x, blk = blockIdx.x, nbk = gridDim.x;
    int w = tid >> 5, lane = tid & 31;
    int r0 = (tid & 7) * 4, c0 = (tid >> 3) * 8;
    int gen = 0;

    // ---- setup ----
    if (blk < 32) {
        for (int e = tid; e < 512; e += 256) g_x[blk * 512 + e] = spec[e];
        float* seq = out + (size_t)blk * (17 * Vc) + (size_t)16 * Vc;
        for (int v = tid; v < Vc; v += 256) seq[v] = (v == 0) ? 1.f : 0.f;
    }
    if (blk < 128) {
        int l = blk >> 5, b = blk & 31;
        for (int e = tid; e < 512; e += 256) s_q[e] = enc[b * 512 + e];
        __syncthreads();
        for (int e = w; e < 512; e += 8) {
            const float* wr = caqw + ((size_t)l * 1536 + 1024 + e) * 512;
            float a0=0,a1=0,a2=0,a3=0;
            for (int k = lane; k < 512; k += 128) {
                a0 += wr[k]*s_q[k];       a1 += wr[k+32]*s_q[k+32];
                a2 += wr[k+64]*s_q[k+64]; a3 += wr[k+96]*s_q[k+96];
            }
            float acc = a0+a1+a2+a3;
            #pragma unroll
            for (int o = 16; o; o >>= 1) acc += __shfl_xor_sync(0xffffffffu, acc, o);
            if (lane == 0) s_o[e] = acc + caqb[l * 1536 + 1024 + e];
        }
        __syncthreads();
        for (int e = w; e < 512; e += 8) {
            const float* wr = caow + ((size_t)l * 512 + e) * 512;
            float a0=0,a1=0,a2=0,a3=0;
            for (int k = lane; k < 512; k += 128) {
                a0 += wr[k]*s_o[k];       a1 += wr[k+32]*s_o[k+32];
                a2 += wr[k+64]*s_o[k+64]; a3 += wr[k+96]*s_o[k+96];
            }
            float acc = a0+a1+a2+a3;
            #pragma unroll
            for (int o = 16; o; o >>= 1) acc += __shfl_xor_sync(0xffffffffu, acc, o);
            if (lane == 0) g_ca[((size_t)l * 32 + b) * 512 + e] = acc + caob[l * 512 + e];
        }
    }
    gsync(gen);

    for (int s = 0; s < Tc; s++) {
        for (int l = 0; l < 4; l++) {
            // P1: qkv partials (96 jobs = 6 nt x 16 ks)
            for (int j = blk; j < 6 * KSQ; j += nbk) {
                int ks = j & 15, nt = j >> 4;
                float acc[4][8] = {};
                __syncthreads();
                stage_X(g_x, 512, ks * 32);
                stage_W_A(saqw + (size_t)l * 1536 * 512, 512, nt * 256, ks * 32);
                __syncthreads();
                inner_A(acc, r0, c0);
                store_acc(acc, r0, c0, g_qkvp + (size_t)ks * 32 * 1536, 1536, nt * 256);
            }
            gsync(gen);
            // P2: attention core only (32 blocks)
            if (blk < 32) {
                int b = blk;
                const float* bp = saqb + l * 1536;
                for (int e = tid; e < 512; e += 256) {
                    float qq = bp[e], kk = bp[512 + e], vv = bp[1024 + e];
                    #pragma unroll
                    for (int p = 0; p < KSQ; p++) {
                        const float* qp = g_qkvp + ((size_t)p * 32 + b) * 1536;
                        qq += qp[e]; kk += qp[512 + e]; vv += qp[1024 + e];
                    }
                    s_q[e] = qq;
                    g_Kc [((size_t)(l * Tc + s) * Bc + b) * 512 + e] = kk;
                    g_Vcc[((size_t)(l * Tc + s) * Bc + b) * 512 + e] = vv;
                }
                __syncthreads();
                float sc = -1e30f;
                if (lane <= s) {
                    const float* kp = g_Kc + ((size_t)(l * Tc + lane) * Bc + b) * 512 + w * 64;
                    const float* qp = s_q + w * 64;
                    float a0 = 0.f, a1 = 0.f;
                    #pragma unroll
                    for (int d = 0; d < 64; d += 2) { a0 += qp[d]*kp[d]; a1 += qp[d+1]*kp[d+1]; }
                    sc = (a0 + a1) * 0.125f;
                }
                float m = sc;
                #pragma unroll
                for (int o = 16; o; o >>= 1) m = fmaxf(m, __shfl_xor_sync(0xffffffffu, m, o));
                float ex = (lane <= s) ? expf(sc - m) : 0.f;
                float sum = ex;
                #pragma unroll
                for (int o = 16; o; o >>= 1) sum += __shfl_xor_sync(0xffffffffu, sum, o);
                float a = ex / sum;
                float o0 = 0.f, o1 = 0.f;
                for (int j = 0; j <= s; j++) {
                    float aj = __shfl_sync(0xffffffffu, a, j);
                    const float* vp = g_Vcc + ((size_t)(l * Tc + j) * Bc + b) * 512 + w * 64;
                    o0 += aj * vp[lane]; o1 += aj * vp[lane + 32];
                }
                g_attn_o[b * 512 + w * 64 + lane] = o0;
                g_attn_o[b * 512 + w * 64 + lane + 32] = o1;
            }
            gsync(gen);
            // P3: out-proj partials (32 jobs = 2 nt x 16 ks) — tiled GEMM
            for (int j = blk; j < 2 * KSO; j += nbk) {
                int nt = j & 1, ks = j >> 1;
                float acc[4][8] = {};
                __syncthreads();
                stage_X(g_attn_o, 512, ks * 32);
                stage_W_A(saow + (size_t)l * 512 * 512, 512, nt * 256, ks * 32);
                __syncthreads();
                inner_A(acc, r0, c0);
                store_acc(acc, r0, c0, g_opp + (size_t)ks * 32 * 512, 512, nt * 256);
            }
            gsync(gen);
            // P4: residual + LN1 + CA + LN2 (32 blocks)
            if (blk < 32) {
                int b = blk;
                for (int e = tid; e < 512; e += 256) {
                    float v = g_x[b * 512 + e] + saob[l * 512 + e];
                    #pragma unroll
                    for (int p = 0; p < KSO; p++) v += g_opp[((size_t)p * 32 + b) * 512 + e];
                    s_q[e] = v;
                }
                __syncthreads();
                float s1 = 0.f, s2 = 0.f;
                for (int e = tid; e < 512; e += 256) { float v = s_q[e]; s1 += v; s2 += v*v; }
                float2 r = blockSum2(s1, s2);
                float mean = r.x * (1.f/512.f);
                float rstd = rsqrtf(r.y * (1.f/512.f) - mean*mean + 1e-5f);
                for (int e = tid; e < 512; e += 256)
                    s_o[e] = (s_q[e]-mean)*rstd*l1g[l*512+e] + l1b[l*512+e]
                           + g_ca[((size_t)l*32+b)*512+e];
                __syncthreads();
                float t1 = 0.f, t2 = 0.f;
                for (int e = tid; e < 512; e += 256) { float v = s_o[e]; t1 += v; t2 += v*v; }
                r = blockSum2(t1, t2);
                mean = r.x * (1.f/512.f);
                rstd = rsqrtf(r.y * (1.f/512.f) - mean*mean + 1e-5f);
                for (int e = tid; e < 512; e += 256)
                    g_x[b*512+e] = (s_o[e]-mean)*rstd*l2g[l*512+e] + l2b[l*512+e];
            }
            gsync(gen);
            // P5: ff1 partials (128 jobs)
            for (int j = blk; j < 8 * KSF1; j += nbk) {
                int ks = j & 15, nt = j >> 4;
                float acc[4][8] = {};
                __syncthreads();
                stage_X(g_x, 512, ks * 32);
                stage_W_A(w1 + (size_t)l * 2048 * 512, 512, nt * 256, ks * 32);
                __syncthreads();
                inner_A(acc, r0, c0);
                store_acc(acc, r0, c0, g_ff1p + (size_t)ks * 32 * 2048, 2048, nt * 256);
            }
            gsync(gen);
            // P7: ff2 partials with folded gelu (128 jobs)
            for (int j = blk; j < 2 * KSF2; j += nbk) {
                int nt = j & 1, ks = j >> 1;
                int kc = ks * 32;
                float acc[4][8] = {};
                __syncthreads();
                {
                    float (*Xs)[33] = (float(*)[33])s_Xs;
                    for (int i = tid; i < 1024; i += 256) {
                        int r = i >> 5, k = i & 31;
                        float u = b1[l * 2048 + kc + k];
                        #pragma unroll
                        for (int p = 0; p < KSF1; p++)
                            u += g_ff1p[((size_t)(p * 32) + r) * 2048 + kc + k];
                        Xs[r][k] = geluf(u);
                    }
                }
                stage_W_A(w2 + (size_t)l * 512 * 2048, 2048, nt * 256, kc);
                __syncthreads();
                inner_A(acc, r0, c0);
                store_acc(acc, r0, c0, g_ff2p + (size_t)ks * 32 * 512, 512, nt * 256);
            }
            gsync(gen);
            // P8: residual + LN3 (32 blocks)
            if (blk < 32) {
                int b = blk;
                for (int e = tid; e < 512; e += 256) {
                    float v = g_x[b * 512 + e] + b2[l * 512 + e];
                    #pragma unroll
                    for (int p = 0; p < KSF2; p++) v += g_ff2p[((size_t)p * 32 + b) * 512 + e];
                    s_q[e] = v;
                }
                __syncthreads();
                float s1 = 0.f, s2 = 0.f;
                for (int e = tid; e < 512; e += 256) { float v = s_q[e]; s1 += v; s2 += v*v; }
                float2 r = blockSum2(s1, s2);
                float mean = r.x * (1.f/512.f);
                float rstd = rsqrtf(r.y * (1.f/512.f) - mean*mean + 1e-5f);
                for (int e = tid; e < 512; e += 256)
                    g_x[b*512+e] = (s_q[e]-mean)*rstd*l3g[l*512+e] + l3b[l*512+e];
            }
            gsync(gen);
        }
        // P9: logits partials (128 jobs)
        for (int j = blk; j < 32 * KSL; j += nbk) {
            int ks = j & 3, nt = j >> 2;
            float acc[4][8] = {};
            for (int kc = ks * 128; kc < ks * 128 + 128; kc += 32) {
                __syncthreads();
                stage_X(g_x, 512, kc);
                stage_W_A(outw, 512, nt * 256, kc);
                __syncthreads();
                inner_A(acc, r0, c0);
            }
            store_acc(acc, r0, c0, g_logp + (size_t)ks * 32 * Vc, Vc, nt * 256);
        }
        gsync(gen);
        // P10: softmaxes + outputs + sample (32 blocks)
        if (blk < 32) {
            int b = blk;
            const float* gp = gum + ((size_t)s * Bc + b) * Vc;
            float* lg = g_logits + (size_t)b * Vc;
            float mx1 = -1e30f, mx2 = -1e30f;
            for (int v = tid; v < Vc; v += 256) {
                float x = outb[v];
                #pragma unroll
                for (int p = 0; p < KSL; p++) x += g_logp[((size_t)p * 32 + b) * Vc + v];
                lg[v] = x;
                mx1 = fmaxf(mx1, x);
                mx2 = fmaxf(mx2, x + gp[v]);
            }
            float2 M = blockMax2(mx1, mx2);
            float z1 = 0.f, z2 = 0.f;
            for (int v = tid; v < Vc; v += 256) {
                float x = lg[v];
                z1 += expf(x - M.x);
                z2 += expf(x + gp[v] - M.y);
            }
            float2 Z = blockSum2(z1, z2);
            float i1 = 1.f / Z.x, i2 = 1.f / Z.y;
            float* seq = out + (size_t)b * (17 * Vc) + (size_t)s * Vc;
            float* dst = out + (size_t)Bc * 17 * Vc + ((size_t)s * Bc + b) * Vc;
            float* smp = g_sample + (size_t)b * Vc;
            for (int v = tid; v < Vc; v += 256) {
                float x = lg[v];
                dst[v] = expf(x - M.x) * i1;
                float sv = expf(x + gp[v] - M.y) * i2;
                seq[v] = sv;
                smp[v] = sv;
            }
        }
        gsync(gen);
        if (s < Tc - 1) {
            // P11: embed partials (128 jobs)
            for (int j = blk; j < 2 * KSE; j += nbk) {
                int nt = j & 1, ks = j >> 1;
                float acc[4][8] = {};
                for (int kc = ks * 128; kc < ks * 128 + 128; kc += 32) {
                    __syncthreads();
                    stage_X(g_sample, Vc, kc);
                    stage_W_B(embw, 512, nt * 256, kc);
                    __syncthreads();
                    inner_B(acc, r0, c0);
                }
                store_acc(acc, r0, c0, g_embp + (size_t)ks * 32 * 512, 512, nt * 256);
            }
            gsync(gen);
            // P12: x = sum(embed partials) * sqrt(E) (32 blocks)
            if (blk < 32) {
                int b = blk;
                for (int e = tid; e < 512; e += 256) {
                    float a = 0.f;
                    #pragma unroll
                    for (int p = 0; p < KSE; p++) a += g_embp[((size_t)p * 32 + b) * 512 + e];
                    g_x[b * 512 + e] = a * EMB_SCALE;
                }
            }
            gsync(gen);
        }
    }

    // ---- reset barrier state so every graph replay starts identically ----
    if (tid == 0) {
        if (blk == 0) g_gen = 0; else g_flags[blk] = 0;
    }
}

extern "C" void kernel_launch(void* const* d_in, const int* in_sizes, int n_in,
                              void* d_out, int out_size) {
    const float* enc  = (const float*)d_in[0];
    const float* spec = (const float*)d_in[1];
    const float* embw = (const float*)d_in[2];
    const float* outw = (const float*)d_in[3];
    const float* outb = (const float*)d_in[4];
    const float* gum  = (const float*)d_in[5];
    const float* saqw = (const float*)d_in[6];
    const float* saqb = (const float*)d_in[7];
    const float* saow = (const float*)d_in[8];
    const float* saob = (const float*)d_in[9];
    const float* caqw = (const float*)d_in[10];
    const float* caqb = (const float*)d_in[11];
    const float* caow = (const float*)d_in[12];
    const float* caob = (const float*)d_in[13];
    const float* l1g  = (const float*)d_in[14];
    const float* l1b  = (const float*)d_in[15];
    const float* l2g  = (const float*)d_in[16];
    const float* l2b  = (const float*)d_in[17];
    const float* l3g  = (const float*)d_in[18];
    const float* l3b  = (const float*)d_in[19];
    const float* w1   = (const float*)d_in[20];
    const float* b1   = (const float*)d_in[21];
    const float* w2   = (const float*)d_in[22];
    const float* b2   = (const float*)d_in[23];

    int dev = 0;
    cudaGetDevice(&dev);
    int sms = 0;
    cudaDeviceGetAttribute(&sms, cudaDevAttrMultiProcessorCount, dev);
    if (sms < 1) sms = 148;
    if (sms > 256) sms = 256;

    mega<<<sms, 256>>>(enc, spec, embw, outw, outb, gum,
                       saqw, saqb, saow, saob, caqw, caqb, caow, caob,
                       l1g, l1b, l2g, l2b, l3g, l3b, w1, b1, w2, b2,
                       (float*)d_out);
}

// round 15
// speedup vs baseline: 2.5485x; 1.1515x over previous
#include <cuda_runtime.h>
#include <math.h>
#include <stdint.h>

#define Bc 32
#define Vc 8192
#define Tc 16
#define EMB_SCALE 22.627416997969522f
#define KSQ 16
#define KSO 16
#define KSF1 16
#define KSF2 64
#define KSL 4
#define KSE 64

__device__ float g_x[Bc * 512];
__device__ float g_attn_o[Bc * 512];
__device__ float g_qkvp[KSQ * Bc * 1536];
__device__ float g_opp[KSO * Bc * 512];
__device__ float g_ff1p[KSF1 * Bc * 2048];
__device__ float g_ff2p[KSF2 * Bc * 512];
__device__ float g_logp[KSL * Bc * Vc];
__device__ float g_embp[KSE * Bc * 512];
__device__ float g_logits[Bc * Vc];
__device__ float g_sample[Bc * Vc];
__device__ float g_ca[4 * Bc * 512];
__device__ float g_Kc[4 * Tc * Bc * 512];
__device__ float g_Vcc[4 * Tc * Bc * 512];

__device__ int g_count;
__device__ volatile int g_gen;

// Unified smem: two staging buffers, each [X: 32x17 = 544][W: 4352 (256x17 or 16x260)]
__shared__ __align__(16) float s_buf[2][4896];
#define SQ (s_buf[0])            // alias for small-phase scratch (512 floats)
#define SO (s_buf[0] + 512)      // alias (512 floats)

// replay-safe atomic barrier (R5-proven) + nanosleep backoff in the spin
__device__ __forceinline__ void gsync() {
    __threadfence();
    __syncthreads();
    if (threadIdx.x == 0) {
        int gen = g_gen;
        if (atomicAdd(&g_count, 1) == (int)gridDim.x - 1) {
            g_count = 0;
            __threadfence();
            g_gen = gen + 1;
        } else {
            while (g_gen == gen) { __nanosleep(64); }
        }
        __threadfence();
    }
    __syncthreads();
}

__device__ __forceinline__ float2 blockSum2(float a, float b) {
    __shared__ float sh[16];
    #pragma unroll
    for (int o = 16; o; o >>= 1) {
        a += __shfl_xor_sync(0xffffffffu, a, o);
        b += __shfl_xor_sync(0xffffffffu, b, o);
    }
    int w = threadIdx.x >> 5;
    if ((threadIdx.x & 31) == 0) { sh[w] = a; sh[8 + w] = b; }
    __syncthreads();
    float ra = sh[0]+sh[1]+sh[2]+sh[3]+sh[4]+sh[5]+sh[6]+sh[7];
    float rb = sh[8]+sh[9]+sh[10]+sh[11]+sh[12]+sh[13]+sh[14]+sh[15];
    __syncthreads();
    return make_float2(ra, rb);
}

__device__ __forceinline__ float2 blockMax2(float a, float b) {
    __shared__ float sh[16];
    #pragma unroll
    for (int o = 16; o; o >>= 1) {
        a = fmaxf(a, __shfl_xor_sync(0xffffffffu, a, o));
        b = fmaxf(b, __shfl_xor_sync(0xffffffffu, b, o));
    }
    int w = threadIdx.x >> 5;
    if ((threadIdx.x & 31) == 0) { sh[w] = a; sh[8 + w] = b; }
    __syncthreads();
    float ra = sh[0], rb = sh[8];
    #pragma unroll
    for (int i = 1; i < 8; i++) { ra = fmaxf(ra, sh[i]); rb = fmaxf(rb, sh[8+i]); }
    __syncthreads();
    return make_float2(ra, rb);
}

__device__ __forceinline__ float geluf(float x) {
    return 0.5f * x * (1.0f + erff(x * 0.70710678118654752f));
}

__device__ __forceinline__ uint32_t smaddr(const void* p) {
    return (uint32_t)__cvta_generic_to_shared(p);
}
__device__ __forceinline__ void cpa4(uint32_t dst, const float* src) {
    asm volatile("cp.async.ca.shared.global [%0], [%1], 4;" :: "r"(dst), "l"(src));
}
#define CP_COMMIT() asm volatile("cp.async.commit_group;")
#define CP_WAIT1()  asm volatile("cp.async.wait_group 1;")
#define CP_WAIT0()  asm volatile("cp.async.wait_group 0;")

// ---- async staging of a 16-k chunk ----
__device__ __forceinline__ void stX(int buf, const float* __restrict__ X, int ldx, int kc) {
    float* Xs = s_buf[buf];
    int t = threadIdx.x;
    #pragma unroll
    for (int i = 0; i < 2; i++) {
        int f = t + i * 256, r = f >> 4, k = f & 15;
        cpa4(smaddr(&Xs[r * 17 + k]), X + (size_t)r * ldx + kc + k);
    }
}
__device__ __forceinline__ void stWA(int buf, const float* __restrict__ W, int ldw, int nb, int kc) {
    float* Ws = s_buf[buf] + 544;
    int t = threadIdx.x;
    #pragma unroll
    for (int i = 0; i < 16; i++) {
        int f = t + i * 256, c = f >> 4, k = f & 15;
        cpa4(smaddr(&Ws[c * 17 + k]), W + (size_t)(nb + c) * ldw + kc + k);
    }
}
__device__ __forceinline__ void stWB(int buf, const float* __restrict__ W, int nb, int kc) {
    float* Wk = s_buf[buf] + 544;   // [16][260]
    int t = threadIdx.x;
    #pragma unroll
    for (int i = 0; i < 16; i++) {
        int f = t + i * 256, k = f >> 8, c = f & 255;
        cpa4(smaddr(&Wk[k * 260 + c]), W + (size_t)(kc + k) * 512 + nb + c);
    }
}

__device__ __forceinline__ void inner16A(float acc[4][8], int buf, int r0, int c0) {
    const float* Xs = s_buf[buf];
    const float* Ws = s_buf[buf] + 544;
    #pragma unroll
    for (int k = 0; k < 16; k++) {
        float xa[4], wa[8];
        #pragma unroll
        for (int i = 0; i < 4; i++) xa[i] = Xs[(r0 + i) * 17 + k];
        #pragma unroll
        for (int j = 0; j < 8; j++) wa[j] = Ws[(c0 + j) * 17 + k];
        #pragma unroll
        for (int i = 0; i < 4; i++)
            #pragma unroll
            for (int j = 0; j < 8; j++) acc[i][j] += xa[i] * wa[j];
    }
}
__device__ __forceinline__ void inner16B(float acc[4][8], int buf, int r0, int c0) {
    const float* Xs = s_buf[buf];
    const float* Wk = s_buf[buf] + 544;
    #pragma unroll
    for (int k = 0; k < 16; k++) {
        float xa[4], wa[8];
        #pragma unroll
        for (int i = 0; i < 4; i++) xa[i] = Xs[(r0 + i) * 17 + k];
        #pragma unroll
        for (int j = 0; j < 8; j++) wa[j] = Wk[k * 260 + c0 + j];
        #pragma unroll
        for (int i = 0; i < 4; i++)
            #pragma unroll
            for (int j = 0; j < 8; j++) acc[i][j] += xa[i] * wa[j];
    }
}

__device__ __forceinline__ void store_acc(float acc[4][8], int r0, int c0,
                                          float* __restrict__ C, int ldc, int nb) {
    #pragma unroll
    for (int i = 0; i < 4; i++) {
        float4* p = (float4*)(C + (size_t)(r0 + i) * ldc + nb + c0);
        p[0] = make_float4(acc[i][0], acc[i][1], acc[i][2], acc[i][3]);
        p[1] = make_float4(acc[i][4], acc[i][5], acc[i][6], acc[i][7]);
    }
}

// pipelined job: C_tile = X[32, k0..k0+NC*16) @ W[nb..nb+256, ...]^T (row-major W)
__device__ void runjobA(const float* __restrict__ X, int ldx,
                        const float* __restrict__ W, int ldw,
                        int nb, int k0, int NC,
                        float* __restrict__ C, int ldc, int r0, int c0) {
    float acc[4][8] = {};
    stX(0, X, ldx, k0);
    stWA(0, W, ldw, nb, k0);
    CP_COMMIT();
    for (int c = 0; c < NC; c++) {
        if (c + 1 < NC) {
            stX((c + 1) & 1, X, ldx, k0 + (c + 1) * 16);
            stWA((c + 1) & 1, W, ldw, nb, k0 + (c + 1) * 16);
            CP_COMMIT();
            CP_WAIT1();
        } else {
            CP_WAIT0();
        }
        __syncthreads();
        inner16A(acc, c & 1, r0, c0);
        __syncthreads();
    }
    store_acc(acc, r0, c0, C, ldc, nb);
}

__global__ __launch_bounds__(256, 1) void mega(
        const float* __restrict__ enc,  const float* __restrict__ spec,
        const float* __restrict__ embw, const float* __restrict__ outw,
        const float* __restrict__ outb, const float* __restrict__ gum,
        const float* __restrict__ saqw, const float* __restrict__ saqb,
        const float* __restrict__ saow, const float* __restrict__ saob,
        const float* __restrict__ caqw, const float* __restrict__ caqb,
        const float* __restrict__ caow, const float* __restrict__ caob,
        const float* __restrict__ l1g,  const float* __restrict__ l1b,
        const float* __restrict__ l2g,  const float* __restrict__ l2b,
        const float* __restrict__ l3g,  const float* __restrict__ l3b,
        const float* __restrict__ w1,   const float* __restrict__ b1,
        const float* __restrict__ w2,   const float* __restrict__ b2,
        float* __restrict__ out) {
    int tid = threadIdx.x, blk = blockIdx.x, nbk = gridDim.x;
    int w = tid >> 5, lane = tid & 31;
    int r0 = (tid & 7) * 4, c0 = (tid >> 3) * 8;

    // ---- setup ----
    if (blk < 32) {
        for (int e = tid; e < 512; e += 256) g_x[blk * 512 + e] = spec[e];
        float* seq = out + (size_t)blk * (17 * Vc) + (size_t)16 * Vc;
        for (int v = tid; v < Vc; v += 256) seq[v] = (v == 0) ? 1.f : 0.f;
    }
    if (blk < 128) {
        int l = blk >> 5, b = blk & 31;
        for (int e = tid; e < 512; e += 256) SQ[e] = enc[b * 512 + e];
        __syncthreads();
        for (int e = w; e < 512; e += 8) {
            const float* wr = caqw + ((size_t)l * 1536 + 1024 + e) * 512;
            float a0=0,a1=0,a2=0,a3=0;
            for (int k = lane; k < 512; k += 128) {
                a0 += wr[k]*SQ[k];       a1 += wr[k+32]*SQ[k+32];
                a2 += wr[k+64]*SQ[k+64]; a3 += wr[k+96]*SQ[k+96];
            }
            float acc = a0+a1+a2+a3;
            #pragma unroll
            for (int o = 16; o; o >>= 1) acc += __shfl_xor_sync(0xffffffffu, acc, o);
            if (lane == 0) SO[e] = acc + caqb[l * 1536 + 1024 + e];
        }
        __syncthreads();
        for (int e = w; e < 512; e += 8) {
            const float* wr = caow + ((size_t)l * 512 + e) * 512;
            float a0=0,a1=0,a2=0,a3=0;
            for (int k = lane; k < 512; k += 128) {
                a0 += wr[k]*SO[k];       a1 += wr[k+32]*SO[k+32];
                a2 += wr[k+64]*SO[k+64]; a3 += wr[k+96]*SO[k+96];
            }
            float acc = a0+a1+a2+a3;
            #pragma unroll
            for (int o = 16; o; o >>= 1) acc += __shfl_xor_sync(0xffffffffu, acc, o);
            if (lane == 0) g_ca[((size_t)l * 32 + b) * 512 + e] = acc + caob[l * 512 + e];
        }
    }
    gsync();

    for (int s = 0; s < Tc; s++) {
        for (int l = 0; l < 4; l++) {
            // P1: qkv partials (96 jobs = 6 nt x 16 ks, k=32 pipelined as 2x16)
            for (int j = blk; j < 6 * KSQ; j += nbk) {
                int ks = j & 15, nt = j >> 4;
                runjobA(g_x, 512, saqw + (size_t)l * 1536 * 512, 512,
                        nt * 256, ks * 32, 2,
                        g_qkvp + (size_t)ks * 32 * 1536, 1536, r0, c0);
            }
            gsync();
            // P2: attention core (32 blocks)
            if (blk < 32) {
                int b = blk;
                const float* bp = saqb + l * 1536;
                for (int e = tid; e < 512; e += 256) {
                    float qq = bp[e], kk = bp[512 + e], vv = bp[1024 + e];
                    #pragma unroll
                    for (int p = 0; p < KSQ; p++) {
                        const float* qp = g_qkvp + ((size_t)p * 32 + b) * 1536;
                        qq += qp[e]; kk += qp[512 + e]; vv += qp[1024 + e];
                    }
                    SQ[e] = qq;
                    g_Kc [((size_t)(l * Tc + s) * Bc + b) * 512 + e] = kk;
                    g_Vcc[((size_t)(l * Tc + s) * Bc + b) * 512 + e] = vv;
                }
                __syncthreads();
                float sc = -1e30f;
                if (lane <= s) {
                    const float* kp = g_Kc + ((size_t)(l * Tc + lane) * Bc + b) * 512 + w * 64;
                    const float* qp = SQ + w * 64;
                    float a0 = 0.f, a1 = 0.f;
                    #pragma unroll
                    for (int d = 0; d < 64; d += 2) { a0 += qp[d]*kp[d]; a1 += qp[d+1]*kp[d+1]; }
                    sc = (a0 + a1) * 0.125f;
                }
                float m = sc;
                #pragma unroll
                for (int o = 16; o; o >>= 1) m = fmaxf(m, __shfl_xor_sync(0xffffffffu, m, o));
                float ex = (lane <= s) ? expf(sc - m) : 0.f;
                float sum = ex;
                #pragma unroll
                for (int o = 16; o; o >>= 1) sum += __shfl_xor_sync(0xffffffffu, sum, o);
                float a = ex / sum;
                float o0 = 0.f, o1 = 0.f;
                for (int j = 0; j <= s; j++) {
                    float aj = __shfl_sync(0xffffffffu, a, j);
                    const float* vp = g_Vcc + ((size_t)(l * Tc + j) * Bc + b) * 512 + w * 64;
                    o0 += aj * vp[lane]; o1 += aj * vp[lane + 32];
                }
                g_attn_o[b * 512 + w * 64 + lane] = o0;
                g_attn_o[b * 512 + w * 64 + lane + 32] = o1;
            }
            gsync();
            // P3: out-proj partials (32 jobs = 2 nt x 16 ks, k=32)
            for (int j = blk; j < 2 * KSO; j += nbk) {
                int nt = j & 1, ks = j >> 1;
                runjobA(g_attn_o, 512, saow + (size_t)l * 512 * 512, 512,
                        nt * 256, ks * 32, 2,
                        g_opp + (size_t)ks * 32 * 512, 512, r0, c0);
            }
            gsync();
            // P4: residual + LN1 + CA + LN2 (32 blocks)
            if (blk < 32) {
                int b = blk;
                for (int e = tid; e < 512; e += 256) {
                    float v = g_x[b * 512 + e] + saob[l * 512 + e];
                    #pragma unroll
                    for (int p = 0; p < KSO; p++) v += g_opp[((size_t)p * 32 + b) * 512 + e];
                    SQ[e] = v;
                }
                __syncthreads();
                float s1 = 0.f, s2 = 0.f;
                for (int e = tid; e < 512; e += 256) { float v = SQ[e]; s1 += v; s2 += v*v; }
                float2 r = blockSum2(s1, s2);
                float mean = r.x * (1.f/512.f);
                float rstd = rsqrtf(r.y * (1.f/512.f) - mean*mean + 1e-5f);
                for (int e = tid; e < 512; e += 256)
                    SO[e] = (SQ[e]-mean)*rstd*l1g[l*512+e] + l1b[l*512+e]
                          + g_ca[((size_t)l*32+b)*512+e];
                __syncthreads();
                float t1 = 0.f, t2 = 0.f;
                for (int e = tid; e < 512; e += 256) { float v = SO[e]; t1 += v; t2 += v*v; }
                r = blockSum2(t1, t2);
                mean = r.x * (1.f/512.f);
                rstd = rsqrtf(r.y * (1.f/512.f) - mean*mean + 1e-5f);
                for (int e = tid; e < 512; e += 256)
                    g_x[b*512+e] = (SO[e]-mean)*rstd*l2g[l*512+e] + l2b[l*512+e];
            }
            gsync();
            // P5: ff1 partials (128 jobs = 8 nt x 16 ks, k=32)
            for (int j = blk; j < 8 * KSF1; j += nbk) {
                int ks = j & 15, nt = j >> 4;
                runjobA(g_x, 512, w1 + (size_t)l * 2048 * 512, 512,
                        nt * 256, ks * 32, 2,
                        g_ff1p + (size_t)ks * 32 * 2048, 2048, r0, c0);
            }
            gsync();
            // P7: ff2 partials, gelu-staged X, W async-pipelined (128 jobs = 2 nt x 64 ks)
            for (int j = blk; j < 2 * KSF2; j += nbk) {
                int nt = j & 1, ks = j >> 1;
                int k0 = ks * 32;
                float acc[4][8] = {};
                stWA(0, w2 + (size_t)l * 512 * 2048, 2048, nt * 256, k0);
                CP_COMMIT();
                #pragma unroll
                for (int c = 0; c < 2; c++) {
                    if (c == 0) {
                        stWA(1, w2 + (size_t)l * 512 * 2048, 2048, nt * 256, k0 + 16);
                        CP_COMMIT();
                    }
                    {   // gelu-stage X chunk c into buf c
                        float* Xs = s_buf[c];
                        int kc = k0 + c * 16;
                        #pragma unroll
                        for (int i = 0; i < 2; i++) {
                            int f = tid + i * 256, r = f >> 4, k = f & 15;
                            float u = b1[l * 2048 + kc + k];
                            #pragma unroll
                            for (int p = 0; p < KSF1; p++)
                                u += g_ff1p[((size_t)(p * 32) + r) * 2048 + kc + k];
                            Xs[r * 17 + k] = geluf(u);
                        }
                    }
                    if (c == 0) { CP_WAIT1(); } else { CP_WAIT0(); }
                    __syncthreads();
                    inner16A(acc, c, r0, c0);
                    __syncthreads();
                }
                store_acc(acc, r0, c0, g_ff2p + (size_t)ks * 32 * 512, 512, nt * 256);
            }
            gsync();
            // P8: residual + LN3 (32 blocks)
            if (blk < 32) {
                int b = blk;
                for (int e = tid; e < 512; e += 256) {
                    float v = g_x[b * 512 + e] + b2[l * 512 + e];
                    #pragma unroll 8
                    for (int p = 0; p < KSF2; p++) v += g_ff2p[((size_t)p * 32 + b) * 512 + e];
                    SQ[e] = v;
                }
                __syncthreads();
                float s1 = 0.f, s2 = 0.f;
                for (int e = tid; e < 512; e += 256) { float v = SQ[e]; s1 += v; s2 += v*v; }
                float2 r = blockSum2(s1, s2);
                float mean = r.x * (1.f/512.f);
                float rstd = rsqrtf(r.y * (1.f/512.f) - mean*mean + 1e-5f);
                for (int e = tid; e < 512; e += 256)
                    g_x[b*512+e] = (SQ[e]-mean)*rstd*l3g[l*512+e] + l3b[l*512+e];
            }
            gsync();
        }
        // P9: logits partials (128 jobs = 32 nt x 4 ks, k=128 as 8x16 pipelined)
        for (int j = blk; j < 32 * KSL; j += nbk) {
            int ks = j & 3, nt = j >> 2;
            runjobA(g_x, 512, outw, 512, nt * 256, ks * 128, 8,
                    g_logp + (size_t)ks * 32 * Vc, Vc, r0, c0);
        }
        gsync();
        // P10: softmaxes + outputs + sample (32 blocks)
        if (blk < 32) {
            int b = blk;
            const float* gp = gum + ((size_t)s * Bc + b) * Vc;
            float* lg = g_logits + (size_t)b * Vc;
            float mx1 = -1e30f, mx2 = -1e30f;
            for (int v = tid; v < Vc; v += 256) {
                float x = outb[v];
                #pragma unroll
                for (int p = 0; p < KSL; p++) x += g_logp[((size_t)p * 32 + b) * Vc + v];
                lg[v] = x;
                mx1 = fmaxf(mx1, x);
                mx2 = fmaxf(mx2, x + gp[v]);
            }
            float2 M = blockMax2(mx1, mx2);
            float z1 = 0.f, z2 = 0.f;
            for (int v = tid; v < Vc; v += 256) {
                float x = lg[v];
                z1 += expf(x - M.x);
                z2 += expf(x + gp[v] - M.y);
            }
            float2 Z = blockSum2(z1, z2);
            float i1 = 1.f / Z.x, i2 = 1.f / Z.y;
            float* seq = out + (size_t)b * (17 * Vc) + (size_t)s * Vc;
            float* dst = out + (size_t)Bc * 17 * Vc + ((size_t)s * Bc + b) * Vc;
            float* smp = g_sample + (size_t)b * Vc;
            for (int v = tid; v < Vc; v += 256) {
                float x = lg[v];
                dst[v] = expf(x - M.x) * i1;
                float sv = expf(x + gp[v] - M.y) * i2;
                seq[v] = sv;
                smp[v] = sv;
            }
        }
        gsync();
        if (s < Tc - 1) {
            // P11: embed partials (128 jobs = 2 nt x 64 ks, k=128 as 8x16 pipelined)
            for (int j = blk; j < 2 * KSE; j += nbk) {
                int nt = j & 1, ks = j >> 1;
                int k0 = ks * 128;
                float acc[4][8] = {};
                stX(0, g_sample, Vc, k0);
                stWB(0, embw, nt * 256, k0);
                CP_COMMIT();
                for (int c = 0; c < 8; c++) {
                    if (c + 1 < 8) {
                        stX((c + 1) & 1, g_sample, Vc, k0 + (c + 1) * 16);
                        stWB((c + 1) & 1, embw, nt * 256, k0 + (c + 1) * 16);
                        CP_COMMIT();
                        CP_WAIT1();
                    } else {
                        CP_WAIT0();
                    }
                    __syncthreads();
                    inner16B(acc, c & 1, r0, c0);
                    __syncthreads();
                }
                store_acc(acc, r0, c0, g_embp + (size_t)ks * 32 * 512, 512, nt * 256);
            }
            gsync();
            // P12: x = sum(embed partials) * sqrt(E) (32 blocks)
            if (blk < 32) {
                int b = blk;
                for (int e = tid; e < 512; e += 256) {
                    float a = 0.f;
                    #pragma unroll 8
                    for (int p = 0; p < KSE; p++) a += g_embp[((size_t)p * 32 + b) * 512 + e];
                    g_x[b * 512 + e] = a * EMB_SCALE;
                }
            }
            gsync();
        }
    }
}

extern "C" void kernel_launch(void* const* d_in, const int* in_sizes, int n_in,
                              void* d_out, int out_size) {
    const float* enc  = (const float*)d_in[0];
    const float* spec = (const float*)d_in[1];
    const float* embw = (const float*)d_in[2];
    const float* outw = (const float*)d_in[3];
    const float* outb = (const float*)d_in[4];
    const float* gum  = (const float*)d_in[5];
    const float* saqw = (const float*)d_in[6];
    const float* saqb = (const float*)d_in[7];
    const float* saow = (const float*)d_in[8];
    const float* saob = (const float*)d_in[9];
    const float* caqw = (const float*)d_in[10];
    const float* caqb = (const float*)d_in[11];
    const float* caow = (const float*)d_in[12];
    const float* caob = (const float*)d_in[13];
    const float* l1g  = (const float*)d_in[14];
    const float* l1b  = (const float*)d_in[15];
    const float* l2g  = (const float*)d_in[16];
    const float* l2b  = (const float*)d_in[17];
    const float* l3g  = (const float*)d_in[18];
    const float* l3b  = (const float*)d_in[19];
    const float* w1   = (const float*)d_in[20];
    const float* b1   = (const float*)d_in[21];
    const float* w2   = (const float*)d_in[22];
    const float* b2   = (const float*)d_in[23];

    int dev = 0;
    cudaGetDevice(&dev);
    int sms = 0;
    cudaDeviceGetAttribute(&sms, cudaDevAttrMultiProcessorCount, dev);
    if (sms < 1) sms = 148;
    if (sms > 256) sms = 256;

    mega<<<sms, 256>>>(enc, spec, embw, outw, outb, gum,
                       saqw, saqb, saow, saob, caqw, caqb, caow, caob,
                       l1g, l1b, l2g, l2b, l3g, l3b, w1, b1, w2, b2,
                       (float*)d_out);
}

// round 17
// speedup vs baseline: 2.7559x; 1.0814x over previous
#include <cuda_runtime.h>
#include <math.h>
#include <stdint.h>

#define Bc 32
#define Vc 8192
#define Tc 16
#define EMB_SCALE 22.627416997969522f
#define KSQ 16
#define KSO 16
#define KSF1 16
#define KSF2 64
#define KSL 4
#define KSE 64
#define NT 512

__device__ float g_x[Bc * 512];
__device__ float g_attn_o[Bc * 512];
__device__ float g_qkvp[KSQ * Bc * 1536];
__device__ float g_opp[KSO * Bc * 512];
__device__ float g_ff1p[KSF1 * Bc * 2048];
__device__ float g_ff2p[KSF2 * Bc * 512];
__device__ float g_logp[KSL * Bc * Vc];
__device__ float g_embp[KSE * Bc * 512];
__device__ float g_logits[Bc * Vc];
__device__ float g_sample[Bc * Vc];
__device__ float g_ca[4 * Bc * 512];
__device__ float g_Kc[4 * Tc * Bc * 512];
__device__ float g_Vcc[4 * Tc * Bc * 512];

__device__ int g_count;
__device__ volatile int g_gen;

// Unified smem: two staging buffers, each [X: 32x17 = 544][W: 4352 (256x17 or 16x260)]
__shared__ __align__(16) float s_buf[2][4896];
#define SQ (s_buf[0])            // alias for small-phase scratch (512 floats)
#define SO (s_buf[0] + 512)      // alias (512 floats)

// replay-safe atomic barrier; pure spin (no nanosleep wake quantum)
__device__ __forceinline__ void gsync() {
    __threadfence();
    __syncthreads();
    if (threadIdx.x == 0) {
        int gen = g_gen;
        if (atomicAdd(&g_count, 1) == (int)gridDim.x - 1) {
            g_count = 0;
            __threadfence();
            g_gen = gen + 1;
        } else {
            while (g_gen == gen) { }
        }
        __threadfence();
    }
    __syncthreads();
}

// 512-thread (16-warp) reductions
__device__ __forceinline__ float2 blockSum2(float a, float b) {
    __shared__ float sh[32];
    #pragma unroll
    for (int o = 16; o; o >>= 1) {
        a += __shfl_xor_sync(0xffffffffu, a, o);
        b += __shfl_xor_sync(0xffffffffu, b, o);
    }
    int w = threadIdx.x >> 5;
    if ((threadIdx.x & 31) == 0) { sh[w] = a; sh[16 + w] = b; }
    __syncthreads();
    float ra = 0.f, rb = 0.f;
    #pragma unroll
    for (int i = 0; i < 16; i++) { ra += sh[i]; rb += sh[16 + i]; }
    __syncthreads();
    return make_float2(ra, rb);
}

__device__ __forceinline__ float2 blockMax2(float a, float b) {
    __shared__ float sh[32];
    #pragma unroll
    for (int o = 16; o; o >>= 1) {
        a = fmaxf(a, __shfl_xor_sync(0xffffffffu, a, o));
        b = fmaxf(b, __shfl_xor_sync(0xffffffffu, b, o));
    }
    int w = threadIdx.x >> 5;
    if ((threadIdx.x & 31) == 0) { sh[w] = a; sh[16 + w] = b; }
    __syncthreads();
    float ra = sh[0], rb = sh[16];
    #pragma unroll
    for (int i = 1; i < 16; i++) { ra = fmaxf(ra, sh[i]); rb = fmaxf(rb, sh[16 + i]); }
    __syncthreads();
    return make_float2(ra, rb);
}

__device__ __forceinline__ float geluf(float x) {
    return 0.5f * x * (1.0f + erff(x * 0.70710678118654752f));
}

__device__ __forceinline__ uint32_t smaddr(const void* p) {
    return (uint32_t)__cvta_generic_to_shared(p);
}
__device__ __forceinline__ void cpa4(uint32_t dst, const float* src) {
    asm volatile("cp.async.ca.shared.global [%0], [%1], 4;" :: "r"(dst), "l"(src));
}
#define CP_COMMIT() asm volatile("cp.async.commit_group;")
#define CP_WAIT1()  asm volatile("cp.async.wait_group 1;")
#define CP_WAIT0()  asm volatile("cp.async.wait_group 0;")

// ---- async staging of a 16-k chunk (512 threads) ----
__device__ __forceinline__ void stX(int buf, const float* __restrict__ X, int ldx, int kc) {
    float* Xs = s_buf[buf];
    int t = threadIdx.x;             // 512 elems: 1 per thread
    int r = t >> 4, k = t & 15;
    cpa4(smaddr(&Xs[r * 17 + k]), X + (size_t)r * ldx + kc + k);
}
__device__ __forceinline__ void stWA(int buf, const float* __restrict__ W, int ldw, int nb, int kc) {
    float* Ws = s_buf[buf] + 544;
    int t = threadIdx.x;
    #pragma unroll
    for (int i = 0; i < 8; i++) {
        int f = t + i * NT, c = f >> 4, k = f & 15;
        cpa4(smaddr(&Ws[c * 17 + k]), W + (size_t)(nb + c) * ldw + kc + k);
    }
}
__device__ __forceinline__ void stWB(int buf, const float* __restrict__ W, int nb, int kc) {
    float* Wk = s_buf[buf] + 544;   // [16][260]
    int t = threadIdx.x;
    #pragma unroll
    for (int i = 0; i < 8; i++) {
        int f = t + i * NT, k = f >> 8, c = f & 255;
        cpa4(smaddr(&Wk[k * 260 + c]), W + (size_t)(kc + k) * 512 + nb + c);
    }
}

__device__ __forceinline__ void inner16A(float acc[4][4], int buf, int r0, int c0) {
    const float* Xs = s_buf[buf];
    const float* Ws = s_buf[buf] + 544;
    #pragma unroll
    for (int k = 0; k < 16; k++) {
        float xa[4], wa[4];
        #pragma unroll
        for (int i = 0; i < 4; i++) xa[i] = Xs[(r0 + i) * 17 + k];
        #pragma unroll
        for (int j = 0; j < 4; j++) wa[j] = Ws[(c0 + j) * 17 + k];
        #pragma unroll
        for (int i = 0; i < 4; i++)
            #pragma unroll
            for (int j = 0; j < 4; j++) acc[i][j] += xa[i] * wa[j];
    }
}
__device__ __forceinline__ void inner16B(float acc[4][4], int buf, int r0, int c0) {
    const float* Xs = s_buf[buf];
    const float* Wk = s_buf[buf] + 544;
    #pragma unroll
    for (int k = 0; k < 16; k++) {
        float xa[4], wa[4];
        #pragma unroll
        for (int i = 0; i < 4; i++) xa[i] = Xs[(r0 + i) * 17 + k];
        #pragma unroll
        for (int j = 0; j < 4; j++) wa[j] = Wk[k * 260 + c0 + j];
        #pragma unroll
        for (int i = 0; i < 4; i++)
            #pragma unroll
            for (int j = 0; j < 4; j++) acc[i][j] += xa[i] * wa[j];
    }
}

__device__ __forceinline__ void store_acc(float acc[4][4], int r0, int c0,
                                          float* __restrict__ C, int ldc, int nb) {
    #pragma unroll
    for (int i = 0; i < 4; i++) {
        float4* p = (float4*)(C + (size_t)(r0 + i) * ldc + nb + c0);
        p[0] = make_float4(acc[i][0], acc[i][1], acc[i][2], acc[i][3]);
    }
}

// pipelined job: C_tile = X[32, k0..k0+NC*16) @ W[nb..nb+256, ...]^T (row-major W)
__device__ void runjobA(const float* __restrict__ X, int ldx,
                        const float* __restrict__ W, int ldw,
                        int nb, int k0, int NC,
                        float* __restrict__ C, int ldc, int r0, int c0) {
    float acc[4][4] = {};
    stX(0, X, ldx, k0);
    stWA(0, W, ldw, nb, k0);
    CP_COMMIT();
    for (int c = 0; c < NC; c++) {
        if (c + 1 < NC) {
            stX((c + 1) & 1, X, ldx, k0 + (c + 1) * 16);
            stWA((c + 1) & 1, W, ldw, nb, k0 + (c + 1) * 16);
            CP_COMMIT();
            CP_WAIT1();
        } else {
            CP_WAIT0();
        }
        __syncthreads();
        inner16A(acc, c & 1, r0, c0);
        __syncthreads();
    }
    store_acc(acc, r0, c0, C, ldc, nb);
}

__global__ __launch_bounds__(NT, 1) void mega(
        const float* __restrict__ enc,  const float* __restrict__ spec,
        const float* __restrict__ embw, const float* __restrict__ outw,
        const float* __restrict__ outb, const float* __restrict__ gum,
        const float* __restrict__ saqw, const float* __restrict__ saqb,
        const float* __restrict__ saow, const float* __restrict__ saob,
        const float* __restrict__ caqw, const float* __restrict__ caqb,
        const float* __restrict__ caow, const float* __restrict__ caob,
        const float* __restrict__ l1g,  const float* __restrict__ l1b,
        const float* __restrict__ l2g,  const float* __restrict__ l2b,
        const float* __restrict__ l3g,  const float* __restrict__ l3b,
        const float* __restrict__ w1,   const float* __restrict__ b1,
        const float* __restrict__ w2,   const float* __restrict__ b2,
        float* __restrict__ out) {
    int tid = threadIdx.x, blk = blockIdx.x, nbk = gridDim.x;
    int w = tid >> 5, lane = tid & 31;
    int r0 = (tid & 7) * 4, c0 = (tid >> 3) * 4;

    // ---- setup ----
    if (blk < 32) {
        for (int e = tid; e < 512; e += NT) g_x[blk * 512 + e] = spec[e];
        float* seq = out + (size_t)blk * (17 * Vc) + (size_t)16 * Vc;
        for (int v = tid; v < Vc; v += NT) seq[v] = (v == 0) ? 1.f : 0.f;
    }
    if (blk < 128) {
        int l = blk >> 5, b = blk & 31;
        for (int e = tid; e < 512; e += NT) SQ[e] = enc[b * 512 + e];
        __syncthreads();
        for (int e = w; e < 512; e += 16) {
            const float* wr = caqw + ((size_t)l * 1536 + 1024 + e) * 512;
            float a0=0,a1=0,a2=0,a3=0;
            for (int k = lane; k < 512; k += 128) {
                a0 += wr[k]*SQ[k];       a1 += wr[k+32]*SQ[k+32];
                a2 += wr[k+64]*SQ[k+64]; a3 += wr[k+96]*SQ[k+96];
            }
            float acc = a0+a1+a2+a3;
            #pragma unroll
            for (int o = 16; o; o >>= 1) acc += __shfl_xor_sync(0xffffffffu, acc, o);
            if (lane == 0) SO[e] = acc + caqb[l * 1536 + 1024 + e];
        }
        __syncthreads();
        for (int e = w; e < 512; e += 16) {
            const float* wr = caow + ((size_t)l * 512 + e) * 512;
            float a0=0,a1=0,a2=0,a3=0;
            for (int k = lane; k < 512; k += 128) {
                a0 += wr[k]*SO[k];       a1 += wr[k+32]*SO[k+32];
                a2 += wr[k+64]*SO[k+64]; a3 += wr[k+96]*SO[k+96];
            }
            float acc = a0+a1+a2+a3;
            #pragma unroll
            for (int o = 16; o; o >>= 1) acc += __shfl_xor_sync(0xffffffffu, acc, o);
            if (lane == 0) g_ca[((size_t)l * 32 + b) * 512 + e] = acc + caob[l * 512 + e];
        }
    }
    gsync();

    for (int s = 0; s < Tc; s++) {
        for (int l = 0; l < 4; l++) {
            // P1: qkv partials (96 jobs = 6 nt x 16 ks, k=32 pipelined as 2x16)
            for (int j = blk; j < 6 * KSQ; j += nbk) {
                int ks = j & 15, nt = j >> 4;
                runjobA(g_x, 512, saqw + (size_t)l * 1536 * 512, 512,
                        nt * 256, ks * 32, 2,
                        g_qkvp + (size_t)ks * 32 * 1536, 1536, r0, c0);
            }
            gsync();
            // P2: attention core (32 blocks)
            if (blk < 32) {
                int b = blk;
                const float* bp = saqb + l * 1536;
                for (int e = tid; e < 512; e += NT) {
                    float qq = bp[e], kk = bp[512 + e], vv = bp[1024 + e];
                    #pragma unroll
                    for (int p = 0; p < KSQ; p++) {
                        const float* qp = g_qkvp + ((size_t)p * 32 + b) * 1536;
                        qq += qp[e]; kk += qp[512 + e]; vv += qp[1024 + e];
                    }
                    SQ[e] = qq;
                    g_Kc [((size_t)(l * Tc + s) * Bc + b) * 512 + e] = kk;
                    g_Vcc[((size_t)(l * Tc + s) * Bc + b) * 512 + e] = vv;
                }
                __syncthreads();
                if (w < 8) {   // one warp per head
                    float sc = -1e30f;
                    if (lane <= s) {
                        const float* kp = g_Kc + ((size_t)(l * Tc + lane) * Bc + b) * 512 + w * 64;
                        const float* qp = SQ + w * 64;
                        float a0 = 0.f, a1 = 0.f;
                        #pragma unroll
                        for (int d = 0; d < 64; d += 2) { a0 += qp[d]*kp[d]; a1 += qp[d+1]*kp[d+1]; }
                        sc = (a0 + a1) * 0.125f;
                    }
                    float m = sc;
                    #pragma unroll
                    for (int o = 16; o; o >>= 1) m = fmaxf(m, __shfl_xor_sync(0xffffffffu, m, o));
                    float ex = (lane <= s) ? expf(sc - m) : 0.f;
                    float sum = ex;
                    #pragma unroll
                    for (int o = 16; o; o >>= 1) sum += __shfl_xor_sync(0xffffffffu, sum, o);
                    float a = ex / sum;
                    float o0 = 0.f, o1 = 0.f;
                    for (int j = 0; j <= s; j++) {
                        float aj = __shfl_sync(0xffffffffu, a, j);
                        const float* vp = g_Vcc + ((size_t)(l * Tc + j) * Bc + b) * 512 + w * 64;
                        o0 += aj * vp[lane]; o1 += aj * vp[lane + 32];
                    }
                    g_attn_o[b * 512 + w * 64 + lane] = o0;
                    g_attn_o[b * 512 + w * 64 + lane + 32] = o1;
                }
            }
            gsync();
            // P3: out-proj partials (32 jobs = 2 nt x 16 ks, k=32)
            for (int j = blk; j < 2 * KSO; j += nbk) {
                int nt = j & 1, ks = j >> 1;
                runjobA(g_attn_o, 512, saow + (size_t)l * 512 * 512, 512,
                        nt * 256, ks * 32, 2,
                        g_opp + (size_t)ks * 32 * 512, 512, r0, c0);
            }
            gsync();
            // P4: residual + LN1 + CA + LN2 (32 blocks)
            if (blk < 32) {
                int b = blk;
                for (int e = tid; e < 512; e += NT) {
                    float v = g_x[b * 512 + e] + saob[l * 512 + e];
                    #pragma unroll
                    for (int p = 0; p < KSO; p++) v += g_opp[((size_t)p * 32 + b) * 512 + e];
                    SQ[e] = v;
                }
                __syncthreads();
                float s1 = 0.f, s2 = 0.f;
                for (int e = tid; e < 512; e += NT) { float v = SQ[e]; s1 += v; s2 += v*v; }
                float2 r = blockSum2(s1, s2);
                float mean = r.x * (1.f/512.f);
                float rstd = rsqrtf(r.y * (1.f/512.f) - mean*mean + 1e-5f);
                for (int e = tid; e < 512; e += NT)
                    SO[e] = (SQ[e]-mean)*rstd*l1g[l*512+e] + l1b[l*512+e]
                          + g_ca[((size_t)l*32+b)*512+e];
                __syncthreads();
                float t1 = 0.f, t2 = 0.f;
                for (int e = tid; e < 512; e += NT) { float v = SO[e]; t1 += v; t2 += v*v; }
                r = blockSum2(t1, t2);
                mean = r.x * (1.f/512.f);
                rstd = rsqrtf(r.y * (1.f/512.f) - mean*mean + 1e-5f);
                for (int e = tid; e < 512; e += NT)
                    g_x[b*512+e] = (SO[e]-mean)*rstd*l2g[l*512+e] + l2b[l*512+e];
            }
            gsync();
            // P5: ff1 partials (128 jobs = 8 nt x 16 ks, k=32)
            for (int j = blk; j < 8 * KSF1; j += nbk) {
                int ks = j & 15, nt = j >> 4;
                runjobA(g_x, 512, w1 + (size_t)l * 2048 * 512, 512,
                        nt * 256, ks * 32, 2,
                        g_ff1p + (size_t)ks * 32 * 2048, 2048, r0, c0);
            }
            gsync();
            // P7: ff2 partials, gelu-staged X, W async-pipelined (128 jobs = 2 nt x 64 ks)
            for (int j = blk; j < 2 * KSF2; j += nbk) {
                int nt = j & 1, ks = j >> 1;
                int k0 = ks * 32;
                float acc[4][4] = {};
                stWA(0, w2 + (size_t)l * 512 * 2048, 2048, nt * 256, k0);
                CP_COMMIT();
                #pragma unroll
                for (int c = 0; c < 2; c++) {
                    if (c == 0) {
                        stWA(1, w2 + (size_t)l * 512 * 2048, 2048, nt * 256, k0 + 16);
                        CP_COMMIT();
                    }
                    {   // gelu-stage X chunk c into buf c (512 elems, 1/thread)
                        float* Xs = s_buf[c];
                        int kc = k0 + c * 16;
                        int r = tid >> 4, k = tid & 15;
                        float u = b1[l * 2048 + kc + k];
                        #pragma unroll
                        for (int p = 0; p < KSF1; p++)
                            u += g_ff1p[((size_t)(p * 32) + r) * 2048 + kc + k];
                        Xs[r * 17 + k] = geluf(u);
                    }
                    if (c == 0) { CP_WAIT1(); } else { CP_WAIT0(); }
                    __syncthreads();
                    inner16A(acc, c, r0, c0);
                    __syncthreads();
                }
                store_acc(acc, r0, c0, g_ff2p + (size_t)ks * 32 * 512, 512, nt * 256);
            }
            gsync();
            // P8: residual + LN3 (32 blocks)
            if (blk < 32) {
                int b = blk;
                for (int e = tid; e < 512; e += NT) {
                    float v = g_x[b * 512 + e] + b2[l * 512 + e];
                    #pragma unroll 8
                    for (int p = 0; p < KSF2; p++) v += g_ff2p[((size_t)p * 32 + b) * 512 + e];
                    SQ[e] = v;
                }
                __syncthreads();
                float s1 = 0.f, s2 = 0.f;
                for (int e = tid; e < 512; e += NT) { float v = SQ[e]; s1 += v; s2 += v*v; }
                float2 r = blockSum2(s1, s2);
                float mean = r.x * (1.f/512.f);
                float rstd = rsqrtf(r.y * (1.f/512.f) - mean*mean + 1e-5f);
                for (int e = tid; e < 512; e += NT)
                    g_x[b*512+e] = (SQ[e]-mean)*rstd*l3g[l*512+e] + l3b[l*512+e];
            }
            gsync();
        }
        // P9: logits partials (128 jobs = 32 nt x 4 ks, k=128 as 8x16 pipelined)
        for (int j = blk; j < 32 * KSL; j += nbk) {
            int ks = j & 3, nt = j >> 2;
            runjobA(g_x, 512, outw, 512, nt * 256, ks * 128, 8,
                    g_logp + (size_t)ks * 32 * Vc, Vc, r0, c0);
        }
        gsync();
        // P10: softmaxes + outputs + sample (32 blocks)
        if (blk < 32) {
            int b = blk;
            const float* gp = gum + ((size_t)s * Bc + b) * Vc;
            float* lg = g_logits + (size_t)b * Vc;
            float mx1 = -1e30f, mx2 = -1e30f;
            for (int v = tid; v < Vc; v += NT) {
                float x = outb[v];
                #pragma unroll
                for (int p = 0; p < KSL; p++) x += g_logp[((size_t)p * 32 + b) * Vc + v];
                lg[v] = x;
                mx1 = fmaxf(mx1, x);
                mx2 = fmaxf(mx2, x + gp[v]);
            }
            float2 M = blockMax2(mx1, mx2);
            float z1 = 0.f, z2 = 0.f;
            for (int v = tid; v < Vc; v += NT) {
                float x = lg[v];
                z1 += expf(x - M.x);
                z2 += expf(x + gp[v] - M.y);
            }
            float2 Z = blockSum2(z1, z2);
            float i1 = 1.f / Z.x, i2 = 1.f / Z.y;
            float* seq = out + (size_t)b * (17 * Vc) + (size_t)s * Vc;
            float* dst = out + (size_t)Bc * 17 * Vc + ((size_t)s * Bc + b) * Vc;
            float* smp = g_sample + (size_t)b * Vc;
            for (int v = tid; v < Vc; v += NT) {
                float x = lg[v];
                dst[v] = expf(x - M.x) * i1;
                float sv = expf(x + gp[v] - M.y) * i2;
                seq[v] = sv;
                smp[v] = sv;
            }
        }
        gsync();
        if (s < Tc - 1) {
            // P11: embed partials (128 jobs = 2 nt x 64 ks, k=128 as 8x16 pipelined)
            for (int j = blk; j < 2 * KSE; j += nbk) {
                int nt = j & 1, ks = j >> 1;
                int k0 = ks * 128;
                float acc[4][4] = {};
                stX(0, g_sample, Vc, k0);
                stWB(0, embw, nt * 256, k0);
                CP_COMMIT();
                for (int c = 0; c < 8; c++) {
                    if (c + 1 < 8) {
                        stX((c + 1) & 1, g_sample, Vc, k0 + (c + 1) * 16);
                        stWB((c + 1) & 1, embw, nt * 256, k0 + (c + 1) * 16);
                        CP_COMMIT();
                        CP_WAIT1();
                    } else {
                        CP_WAIT0();
                    }
                    __syncthreads();
                    inner16B(acc, c & 1, r0, c0);
                    __syncthreads();
                }
                store_acc(acc, r0, c0, g_embp + (size_t)ks * 32 * 512, 512, nt * 256);
            }
            gsync();
            // P12: x = sum(embed partials) * sqrt(E) (32 blocks)
            if (blk < 32) {
                int b = blk;
                for (int e = tid; e < 512; e += NT) {
                    float a = 0.f;
                    #pragma unroll 8
                    for (int p = 0; p < KSE; p++) a += g_embp[((size_t)p * 32 + b) * 512 + e];
                    g_x[b * 512 + e] = a * EMB_SCALE;
                }
            }
            gsync();
        }
    }
}

extern "C" void kernel_launch(void* const* d_in, const int* in_sizes, int n_in,
                              void* d_out, int out_size) {
    const float* enc  = (const float*)d_in[0];
    const float* spec = (const float*)d_in[1];
    const float* embw = (const float*)d_in[2];
    const float* outw = (const float*)d_in[3];
    const float* outb = (const float*)d_in[4];
    const float* gum  = (const float*)d_in[5];
    const float* saqw = (const float*)d_in[6];
    const float* saqb = (const float*)d_in[7];
    const float* saow = (const float*)d_in[8];
    const float* saob = (const float*)d_in[9];
    const float* caqw = (const float*)d_in[10];
    const float* caqb = (const float*)d_in[11];
    const float* caow = (const float*)d_in[12];
    const float* caob = (const float*)d_in[13];
    const float* l1g  = (const float*)d_in[14];
    const float* l1b  = (const float*)d_in[15];
    const float* l2g  = (const float*)d_in[16];
    const float* l2b  = (const float*)d_in[17];
    const float* l3g  = (const float*)d_in[18];
    const float* l3b  = (const float*)d_in[19];
    const float* w1   = (const float*)d_in[20];
    const float* b1   = (const float*)d_in[21];
    const float* w2   = (const float*)d_in[22];
    const float* b2   = (const float*)d_in[23];

    int dev = 0;
    cudaGetDevice(&dev);
    int sms = 0;
    cudaDeviceGetAttribute(&sms, cudaDevAttrMultiProcessorCount, dev);
    if (sms < 1) sms = 148;
    if (sms > 256) sms = 256;

    mega<<<sms, NT>>>(enc, spec, embw, outw, outb, gum,
                      saqw, saqb, saow, saob, caqw, caqb, caow, caob,
                      l1g, l1b, l2g, l2b, l3g, l3b, w1, b1, w2, b2,
                      (float*)d_out);
}